// round 8
// baseline (speedup 1.0000x reference)
#include <cuda_runtime.h>
#include <math.h>

#define DIM 512
#define MARGIN 1.0f
#define RULE_WEIGHT 0.5f

#define MAX_B   1024
#define MAX_NEG 8192

// Scratch (allocation-free rule: __device__ globals)
__device__ float g_dposm[MAX_B];        // MARGIN + d_pos  (pre-biased)
__device__ float g_dneg[MAX_NEG];
__device__ float g_rule_sum = 0.f;      // ~40 atomic adds; reset by reduce

__device__ __forceinline__ float warp_red(float v) {
#pragma unroll
    for (int o = 16; o; o >>= 1) v += __shfl_xor_sync(0xffffffffu, v, o);
    return v;
}

// TransH distance, he/te register-resident (R1 variant — best measured).
// d = || (he - te + re) - c*w ||,  c = (he.w - te.w)/(w.w)
__device__ __forceinline__ float dist_from_regs(
    const float4 he[4], const float4 te[4],
    const float* __restrict__ rel, const float* __restrict__ nv,
    int r, int lane)
{
    const float4* w4  = reinterpret_cast<const float4*>(nv  + (size_t)r * DIM);
    const float4* re4 = reinterpret_cast<const float4*>(rel + (size_t)r * DIM);
    float4 w[4], re[4];
    float ww = 0.f, hw = 0.f, tw = 0.f;
#pragma unroll
    for (int i = 0; i < 4; i++) {
        w[i]  = w4[lane + 32 * i];
        re[i] = re4[lane + 32 * i];
        ww += w[i].x * w[i].x + w[i].y * w[i].y + w[i].z * w[i].z + w[i].w * w[i].w;
        hw += he[i].x * w[i].x + he[i].y * w[i].y + he[i].z * w[i].z + he[i].w * w[i].w;
        tw += te[i].x * w[i].x + te[i].y * w[i].y + te[i].z * w[i].z + te[i].w * w[i].w;
    }
    ww = warp_red(ww);
    hw = warp_red(hw);
    tw = warp_red(tw);
    float c = (hw - tw) / ww;
    float ss = 0.f;
#pragma unroll
    for (int i = 0; i < 4; i++) {
        float dx = he[i].x - te[i].x + re[i].x - c * w[i].x;
        float dy = he[i].y - te[i].y + re[i].y - c * w[i].y;
        float dz = he[i].z - te[i].z + re[i].z - c * w[i].z;
        float dw = he[i].w - te[i].w + re[i].w - c * w[i].w;
        ss += dx * dx + dy * dy + dz * dz + dw * dw;
    }
    ss = warp_red(ss);
    return sqrtf(ss);
}

// Flat warp-per-task (R1 structure, measured 7.3us).
__global__ void __launch_bounds__(256)
dist_kernel(const int* __restrict__ pos, const int* __restrict__ neg,
            const int* __restrict__ rr1, const int* __restrict__ rr2,
            const float* __restrict__ rconf,
            const float* __restrict__ ent, const float* __restrict__ rel,
            const float* __restrict__ nv,
            int B, int NEG, int NR)
{
    int gw   = (blockIdx.x * blockDim.x + threadIdx.x) >> 5;
    int lane = threadIdx.x & 31;
    if (gw >= B + NEG) return;

    int h, r, t;
    bool is_pos = (gw < B);
    if (is_pos) {
        h = pos[3 * gw]; r = pos[3 * gw + 1]; t = pos[3 * gw + 2];
    } else {
        int k = gw - B;
        h = neg[3 * k]; r = neg[3 * k + 1]; t = neg[3 * k + 2];
    }

    const float4* he4 = reinterpret_cast<const float4*>(ent + (size_t)h * DIM);
    const float4* te4 = reinterpret_cast<const float4*>(ent + (size_t)t * DIM);
    float4 he[4], te[4];
#pragma unroll
    for (int i = 0; i < 4; i++) {
        he[i] = he4[lane + 32 * i];
        te[i] = te4[lane + 32 * i];
    }

    float d = dist_from_regs(he, te, rel, nv, r, lane);

    if (is_pos) {
        // Only rules with rule_r1[j] == r contribute (mask exact-zeros the rest).
        float racc = 0.f;
        for (int j = 0; j < NR; j++) {
            if (rr1[j] == r)
                racc += rconf[j] * dist_from_regs(he, te, rel, nv, rr2[j], lane);
        }
        if (lane == 0) {
            g_dposm[gw] = MARGIN + d;
            if (racc != 0.f) atomicAdd(&g_rule_sum, racc);  // ~40 warps hit
        }
    } else {
        if (lane == 0) g_dneg[gw - B] = d;
    }
}

// Single-pass reduce: no staging, no pre-barrier. Each float4 of g_dneg
// (kb..kb+3) shares one pos index (q>>1 for ratio=8) -> 1 dpos load per vec.
// All loads independent + L2-hot -> one latency round.
__global__ void __launch_bounds__(256)
final_reduce(float* __restrict__ out, int B, int NEG)
{
    __shared__ float sb[256];
    int tid = threadIdx.x;
    int ratio = NEG / B;

    float acc = 0.f;
    const float4* n4 = reinterpret_cast<const float4*>(g_dneg);
    int nv4 = NEG >> 2;
    int vecs_per_pos = ratio >> 2;           // float4s sharing one pos (2 for ratio=8)
    for (int q = tid; q < nv4; q += 256) {
        float4 v = n4[q];
        float pm = g_dposm[q / vecs_per_pos >> 0 ? q / vecs_per_pos : 0]; // q/(ratio/4)
        pm = g_dposm[q / vecs_per_pos];
        float v0 = pm - v.x; acc += (v0 > 0.f) ? v0 : 0.f;
        float v1 = pm - v.y; acc += (v1 > 0.f) ? v1 : 0.f;
        float v2 = pm - v.z; acc += (v2 > 0.f) ? v2 : 0.f;
        float v3 = pm - v.w; acc += (v3 > 0.f) ? v3 : 0.f;
    }
    // tail (NEG not multiple of 4)
    for (int k = (nv4 << 2) + tid; k < NEG; k += 256) {
        float v = g_dposm[k / ratio] - g_dneg[k];
        acc += (v > 0.f) ? v : 0.f;
    }

    sb[tid] = acc;
    __syncthreads();
    for (int s = 128; s; s >>= 1) {
        if (tid < s) sb[tid] += sb[tid + s];
        __syncthreads();
    }
    if (tid == 0) {
        out[0] = sb[0] / (float)NEG + RULE_WEIGHT * g_rule_sum;
        g_rule_sum = 0.f;      // reset for next graph replay (deterministic)
    }
}

extern "C" void kernel_launch(void* const* d_in, const int* in_sizes, int n_in,
                              void* d_out, int out_size)
{
    const int*   pos   = (const int*)d_in[0];
    const int*   neg   = (const int*)d_in[1];
    const int*   rr1   = (const int*)d_in[2];
    const int*   rr2   = (const int*)d_in[3];
    const float* rconf = (const float*)d_in[4];
    const float* ent   = (const float*)d_in[5];
    const float* rel   = (const float*)d_in[6];
    const float* nv    = (const float*)d_in[7];

    int B   = in_sizes[0] / 3;
    int NEG = in_sizes[1] / 3;
    int NR  = in_sizes[2];

    int totalWarps = B + NEG;
    int blocks = (totalWarps * 32 + 255) / 256;

    dist_kernel<<<blocks, 256>>>(pos, neg, rr1, rr2, rconf, ent, rel, nv, B, NEG, NR);
    final_reduce<<<1, 256>>>((float*)d_out, B, NEG);
}

// round 9
// speedup vs baseline: 1.1000x; 1.1000x over previous
#include <cuda_runtime.h>
#include <math.h>

#define DIM 512
#define MARGIN 1.0f
#define RULE_WEIGHT 0.5f

#define MAX_B   1024
#define MAX_NEG 8192

// Scratch (allocation-free rule: __device__ globals)
__device__ float g_dposm[MAX_B];        // MARGIN + d_pos (pre-biased)
__device__ float g_dneg[MAX_NEG];
__device__ float g_rule_sum = 0.f;      // ~40 atomic adds; reset by reduce blk0

__device__ __forceinline__ float warp_red(float v) {
#pragma unroll
    for (int o = 16; o; o >>= 1) v += __shfl_xor_sync(0xffffffffu, v, o);
    return v;
}

// TransH distance, he/te register-resident (R1 variant — best measured).
// d = || (he - te + re) - c*w ||,  c = (he.w - te.w)/(w.w)
__device__ __forceinline__ float dist_from_regs(
    const float4 he[4], const float4 te[4],
    const float* __restrict__ rel, const float* __restrict__ nv,
    int r, int lane)
{
    const float4* w4  = reinterpret_cast<const float4*>(nv  + (size_t)r * DIM);
    const float4* re4 = reinterpret_cast<const float4*>(rel + (size_t)r * DIM);
    float4 w[4], re[4];
    float ww = 0.f, hw = 0.f, tw = 0.f;
#pragma unroll
    for (int i = 0; i < 4; i++) {
        w[i]  = w4[lane + 32 * i];
        re[i] = re4[lane + 32 * i];
        ww += w[i].x * w[i].x + w[i].y * w[i].y + w[i].z * w[i].z + w[i].w * w[i].w;
        hw += he[i].x * w[i].x + he[i].y * w[i].y + he[i].z * w[i].z + he[i].w * w[i].w;
        tw += te[i].x * w[i].x + te[i].y * w[i].y + te[i].z * w[i].z + te[i].w * w[i].w;
    }
    ww = warp_red(ww);
    hw = warp_red(hw);
    tw = warp_red(tw);
    float c = (hw - tw) / ww;
    float ss = 0.f;
#pragma unroll
    for (int i = 0; i < 4; i++) {
        float dx = he[i].x - te[i].x + re[i].x - c * w[i].x;
        float dy = he[i].y - te[i].y + re[i].y - c * w[i].y;
        float dz = he[i].z - te[i].z + re[i].z - c * w[i].z;
        float dw = he[i].w - te[i].w + re[i].w - c * w[i].w;
        ss += dx * dx + dy * dy + dz * dz + dw * dw;
    }
    ss = warp_red(ss);
    return sqrtf(ss);
}

// Flat warp-per-task (R1 structure). Block 0/tid 0 also zeroes out[0] so the
// reduce node can accumulate into it via atomics (kernel-boundary ordering).
__global__ void __launch_bounds__(256)
dist_kernel(const int* __restrict__ pos, const int* __restrict__ neg,
            const int* __restrict__ rr1, const int* __restrict__ rr2,
            const float* __restrict__ rconf,
            const float* __restrict__ ent, const float* __restrict__ rel,
            const float* __restrict__ nv,
            float* __restrict__ out,
            int B, int NEG, int NR)
{
    if (blockIdx.x == 0 && threadIdx.x == 0) out[0] = 0.f;

    int gw   = (blockIdx.x * blockDim.x + threadIdx.x) >> 5;
    int lane = threadIdx.x & 31;
    if (gw >= B + NEG) return;

    int h, r, t;
    bool is_pos = (gw < B);
    if (is_pos) {
        h = pos[3 * gw]; r = pos[3 * gw + 1]; t = pos[3 * gw + 2];
    } else {
        int k = gw - B;
        h = neg[3 * k]; r = neg[3 * k + 1]; t = neg[3 * k + 2];
    }

    const float4* he4 = reinterpret_cast<const float4*>(ent + (size_t)h * DIM);
    const float4* te4 = reinterpret_cast<const float4*>(ent + (size_t)t * DIM);
    float4 he[4], te[4];
#pragma unroll
    for (int i = 0; i < 4; i++) {
        he[i] = he4[lane + 32 * i];
        te[i] = te4[lane + 32 * i];
    }

    float d = dist_from_regs(he, te, rel, nv, r, lane);

    if (is_pos) {
        // Only rules with rule_r1[j] == r contribute (mask exact-zeros the rest).
        float racc = 0.f;
        for (int j = 0; j < NR; j++) {
            if (rr1[j] == r)
                racc += rconf[j] * dist_from_regs(he, te, rel, nv, rr2[j], lane);
        }
        if (lane == 0) {
            g_dposm[gw] = MARGIN + d;
            if (racc != 0.f) atomicAdd(&g_rule_sum, racc);   // ~40 warps hit
        }
    } else {
        if (lane == 0) g_dneg[gw - B] = d;
    }
}

// Multi-block reduce: every thread handles exactly one float4 of g_dneg
// (one L2 latency round across 8 SMs), block-reduces, atomicAdds into out.
// Block 0 folds in the rule sum and resets it for the next graph replay.
__global__ void __launch_bounds__(256)
final_reduce(float* __restrict__ out, int B, int NEG)
{
    __shared__ float sb[256];
    int tid  = threadIdx.x;
    int gt   = blockIdx.x * blockDim.x + tid;
    int ratio = NEG / B;
    float inv_neg = 1.0f / (float)NEG;

    float acc = 0.f;
    int nv4 = NEG >> 2;
    if ((ratio & 3) == 0) {
        int vpp = ratio >> 2;   // float4s per pos index
        const float4* n4 = reinterpret_cast<const float4*>(g_dneg);
        for (int q = gt; q < nv4; q += gridDim.x * blockDim.x) {
            float4 v = n4[q];
            float pm = g_dposm[q / vpp];
            float v0 = pm - v.x; acc += (v0 > 0.f) ? v0 : 0.f;
            float v1 = pm - v.y; acc += (v1 > 0.f) ? v1 : 0.f;
            float v2 = pm - v.z; acc += (v2 > 0.f) ? v2 : 0.f;
            float v3 = pm - v.w; acc += (v3 > 0.f) ? v3 : 0.f;
        }
    } else {
        for (int k = gt; k < NEG; k += gridDim.x * blockDim.x) {
            float v = g_dposm[k / ratio] - g_dneg[k];
            acc += (v > 0.f) ? v : 0.f;
        }
    }

    sb[tid] = acc;
    __syncthreads();
    for (int s = 128; s; s >>= 1) {
        if (tid < s) sb[tid] += sb[tid + s];
        __syncthreads();
    }
    if (tid == 0) {
        float contrib = sb[0] * inv_neg;
        if (blockIdx.x == 0) {
            float rs = g_rule_sum;
            contrib += RULE_WEIGHT * rs;
            g_rule_sum = 0.f;          // reset for next replay (deterministic)
        }
        atomicAdd(out, contrib);
    }
}

extern "C" void kernel_launch(void* const* d_in, const int* in_sizes, int n_in,
                              void* d_out, int out_size)
{
    const int*   pos   = (const int*)d_in[0];
    const int*   neg   = (const int*)d_in[1];
    const int*   rr1   = (const int*)d_in[2];
    const int*   rr2   = (const int*)d_in[3];
    const float* rconf = (const float*)d_in[4];
    const float* ent   = (const float*)d_in[5];
    const float* rel   = (const float*)d_in[6];
    const float* nv    = (const float*)d_in[7];

    int B   = in_sizes[0] / 3;
    int NEG = in_sizes[1] / 3;
    int NR  = in_sizes[2];

    int totalWarps = B + NEG;
    int blocks = (totalWarps * 32 + 255) / 256;

    dist_kernel<<<blocks, 256>>>(pos, neg, rr1, rr2, rconf, ent, rel, nv,
                                 (float*)d_out, B, NEG, NR);

    // One float4 per thread: nv4 = NEG/4 threads total.
    int rthreads = 256;
    int rblocks  = ((NEG >> 2) + rthreads - 1) / rthreads;
    if (rblocks < 1) rblocks = 1;
    final_reduce<<<rblocks, rthreads>>>((float*)d_out, B, NEG);
}